// round 11
// baseline (speedup 1.0000x reference)
#include <cuda_runtime.h>
#include <cuda_fp16.h>
#include <cstdint>
#include <cstddef>

#define Bb 16
#define Ss 2048
#define Dd 1024
#define Hh 1024
#define Mm (Bb*Ss)      // 32768
#define N3 (3*Hh)       // 3072
#define SC 32
#define CH (Ss/SC)      // 64

// ---- device scratch (static: allowed) ----
__device__ __half g_z[(size_t)Mm*Hh];
__device__ __half g_f[(size_t)Mm*Hh];
__device__ __half g_o[(size_t)Mm*Hh];
__device__ __half g_Ah[(size_t)Mm*Dd];
__device__ __half g_Wh[(size_t)N3*Dd];
__device__ float  g_Ac[Bb*SC*Hh];
__device__ float  g_Bc[Bb*SC*Hh];
__device__ float  g_hs[Bb*SC*Hh];

__device__ __forceinline__ uint32_t smem_u32(const void* p){
  uint32_t a;
  asm("{ .reg .u64 t; cvta.to.shared.u64 t, %1; cvt.u32.u64 %0, t; }" : "=r"(a) : "l"(p));
  return a;
}

__device__ __forceinline__ void mma_f16(float* c, const uint32_t* a, const uint32_t* b){
  asm volatile("mma.sync.aligned.m16n8k16.row.col.f32.f16.f16.f32 "
    "{%0,%1,%2,%3}, {%4,%5,%6,%7}, {%8,%9}, {%0,%1,%2,%3};"
    : "+f"(c[0]),"+f"(c[1]),"+f"(c[2]),"+f"(c[3])
    : "r"(a[0]),"r"(a[1]),"r"(a[2]),"r"(a[3]),"r"(b[0]),"r"(b[1]));
}

// ---- f32 -> f16 convert ----
__global__ void to_half_k(const float4* __restrict__ src, uint4* __restrict__ dst, int n8){
  int i = blockIdx.x*blockDim.x + threadIdx.x;
  if (i >= n8) return;
  float4 v0 = src[2*i], v1 = src[2*i+1];
  __half2 h0 = __floats2half2_rn(v0.x, v0.y);
  __half2 h1 = __floats2half2_rn(v0.z, v0.w);
  __half2 h2 = __floats2half2_rn(v1.x, v1.y);
  __half2 h3 = __floats2half2_rn(v1.z, v1.w);
  uint4 u;
  u.x = *(uint32_t*)&h0; u.y = *(uint32_t*)&h1;
  u.z = *(uint32_t*)&h2; u.w = *(uint32_t*)&h3;
  dst[i] = u;
}

// ---- GEMM: 128x128x(BK=64) fp16, cp.async double-buffer, ldmatrix ----
constexpr int BM=128, BN=128, BK=64;
constexpr int KT = Dd/BK;               // 16 k-tiles
constexpr int ROWH = 72;                // halves per smem row (64 + 8 pad) = 144B
constexpr int STG_H = BM*ROWH;          // 9216 halves per operand per stage
constexpr int STAGE_H = 2*STG_H;        // 18432 halves = 36864B per stage
constexpr int NSTG = 2;
constexpr int GEMM_SMEM = NSTG*STAGE_H*2;  // 73728 bytes

__global__ __launch_bounds__(256,2) void gemm_qrnn(
    const __half* __restrict__ A,   // g_Ah [Mm, Dd]
    const __half* __restrict__ W,   // g_Wh [N3, Dd]
    const float* __restrict__ bias)
{
  extern __shared__ __half sm[];
  const int tid  = threadIdx.x;
  const int lane = tid & 31;
  const int warp = tid >> 5;
  const int wm = warp >> 2;       // 0..1
  const int wn = warp & 3;        // 0..3
  const int bm = blockIdx.y * BM;
  const int bn = blockIdx.x * BN;
  const uint32_t smb = smem_u32(sm);

  float acc[4][4][4];
  #pragma unroll
  for (int i=0;i<4;i++)
    #pragma unroll
    for (int j=0;j<4;j++)
      #pragma unroll
      for (int k=0;k<4;k++) acc[i][j][k]=0.f;

  auto issue = [&](int kt, int s){
    __half* as = sm + s*STAGE_H;
    __half* bs = as + STG_H;
    #pragma unroll
    for (int i=0;i<4;i++){
      int idx = tid + i*256;            // 0..1023 : row 0..127, chunk 0..7
      int row = idx >> 3;
      int ch  = idx & 7;
      const __half* ga = A + (size_t)(bm+row)*Dd + kt*BK + ch*8;
      const __half* gb = W + (size_t)(bn+row)*Dd + kt*BK + ch*8;
      uint32_t sa = smem_u32(as + row*ROWH + ch*8);
      uint32_t sb = smem_u32(bs + row*ROWH + ch*8);
      asm volatile("cp.async.cg.shared.global [%0], [%1], 16;" :: "r"(sa), "l"(ga));
      asm volatile("cp.async.cg.shared.global [%0], [%1], 16;" :: "r"(sb), "l"(gb));
    }
  };

  auto compute = [&](int s){
    const uint32_t abase = smb + s*(STAGE_H*2);
    const uint32_t bbase = abase + STG_H*2;
    #pragma unroll
    for (int q=0; q<4; q++){            // 4 k16 chunks in BK=64
      uint32_t a[4][4], b[4][2];
      #pragma unroll
      for (int mi=0;mi<4;mi++){
        int rowA = wm*64 + mi*16 + (lane & 15);
        uint32_t addr = abase + rowA*144 + q*32 + (lane>>4)*16;
        asm volatile("ldmatrix.sync.aligned.m8n8.x4.shared.b16 {%0,%1,%2,%3}, [%4];"
          : "=r"(a[mi][0]),"=r"(a[mi][1]),"=r"(a[mi][2]),"=r"(a[mi][3]) : "r"(addr));
      }
      #pragma unroll
      for (int np=0; np<2; np++){
        int rowB = wn*32 + np*16 + (lane & 7) + ((lane>>4)&1)*8;
        uint32_t addr = bbase + rowB*144 + q*32 + ((lane>>3)&1)*16;
        asm volatile("ldmatrix.sync.aligned.m8n8.x4.shared.b16 {%0,%1,%2,%3}, [%4];"
          : "=r"(b[np*2][0]),"=r"(b[np*2][1]),"=r"(b[np*2+1][0]),"=r"(b[np*2+1][1]) : "r"(addr));
      }
      #pragma unroll
      for (int mi=0;mi<4;mi++)
        #pragma unroll
        for (int ni=0;ni<4;ni++)
          mma_f16(acc[mi][ni], a[mi], b[ni]);
    }
  };

  issue(0,0); asm volatile("cp.async.commit_group;" ::: "memory");

  for (int kt=0; kt<KT; kt++){
    if (kt+1 < KT) issue(kt+1, (kt+1)&1);
    asm volatile("cp.async.commit_group;" ::: "memory");
    asm volatile("cp.async.wait_group 1;" ::: "memory");
    __syncthreads();
    compute(kt&1);
    __syncthreads();
  }

  // Epilogue: bias + activation -> fp16 gate scratch (half2 stores).
  const int gate = bn >> 10;            // 128-col tile lies within one gate
  __half* dst = (gate==0) ? g_z : ((gate==1) ? g_f : g_o);
  const int r0 = bm + wm*64 + (lane>>2);
  const int c0 = bn + wn*32 + (lane&3)*2;
  #pragma unroll
  for (int mi=0;mi<4;mi++){
    #pragma unroll
    for (int ni=0;ni<4;ni++){
      #pragma unroll
      for (int half=0; half<2; half++){
        const int row = r0 + mi*16 + half*8;
        const int col = c0 + ni*8;
        float y0 = acc[mi][ni][half*2+0] + __ldg(&bias[col]);
        float y1 = acc[mi][ni][half*2+1] + __ldg(&bias[col+1]);
        float v0, v1;
        if (gate==0){ v0 = tanhf(y0); v1 = tanhf(y1); }
        else        { v0 = __fdividef(1.f, 1.f+__expf(-y0));
                      v1 = __fdividef(1.f, 1.f+__expf(-y1)); }
        const int hcol = col & (Hh-1);
        *(__half2*)&dst[(size_t)row*Hh + hcol] = __floats2half2_rn(v0, v1);
      }
    }
  }
}

// ---- two-pass chunked scan (half2 vectorized, f32 math) ----
__global__ __launch_bounds__(512) void scanA_k(){
  int b = blockIdx.x / SC, c = blockIdx.x % SC, h2 = threadIdx.x;
  size_t base2 = ((size_t)(b*Ss + c*CH))*(Hh/2) + h2;
  const __half2* Z = (const __half2*)g_z;
  const __half2* F = (const __half2*)g_f;
  float2 A = make_float2(1.f,1.f), hh = make_float2(0.f,0.f);
  #pragma unroll 4
  for (int s=0; s<CH; s++){
    float2 f = __half22float2(F[base2 + (size_t)s*(Hh/2)]);
    float2 z = __half22float2(Z[base2 + (size_t)s*(Hh/2)]);
    hh.x = fmaf(f.x, z.x - hh.x, hh.x);
    hh.y = fmaf(f.y, z.y - hh.y, hh.y);
    A.x *= (1.f - f.x);
    A.y *= (1.f - f.y);
  }
  int o = blockIdx.x*(Hh/2) + h2;
  ((float2*)g_Ac)[o] = A; ((float2*)g_Bc)[o] = hh;
}

__global__ __launch_bounds__(1024) void scanB_k(float* __restrict__ clast, int wr){
  int t = blockIdx.x*blockDim.x + threadIdx.x;   // 16384
  int b = t >> 10, h = t & (Hh-1);
  float hh = 0.f;
  #pragma unroll
  for (int c=0; c<SC; c++){
    int idx = (b*SC + c)*Hh + h;
    g_hs[idx] = hh;
    hh = fmaf(g_Ac[idx], hh, g_Bc[idx]);
  }
  if (wr) clast[t] = hh;
}

__global__ __launch_bounds__(512) void scanC_k(float* __restrict__ out){
  int b = blockIdx.x / SC, c = blockIdx.x % SC, h2 = threadIdx.x;
  size_t base2 = ((size_t)(b*Ss + c*CH))*(Hh/2) + h2;
  const __half2* Z = (const __half2*)g_z;
  const __half2* F = (const __half2*)g_f;
  const __half2* O = (const __half2*)g_o;
  float2 hh = ((const float2*)g_hs)[blockIdx.x*(Hh/2) + h2];
  float2* out2 = (float2*)out;
  #pragma unroll 4
  for (int s=0; s<CH; s++){
    size_t idx = base2 + (size_t)s*(Hh/2);
    float2 f = __half22float2(F[idx]);
    float2 z = __half22float2(Z[idx]);
    float2 o = __half22float2(O[idx]);
    hh.x = fmaf(f.x, z.x - hh.x, hh.x);
    hh.y = fmaf(f.y, z.y - hh.y, hh.y);
    out2[idx] = make_float2(o.x*hh.x, o.y*hh.y);
  }
}

// ---- host ----
extern "C" void kernel_launch(void* const* d_in, const int* in_sizes, int n_in,
                              void* d_out, int out_size) {
  const float* inp  = (const float*)d_in[0];
  const float* W    = (const float*)d_in[1];
  const float* bias = (const float*)d_in[2];
  float* out = (float*)d_out;

  void *pA=nullptr, *pW=nullptr;
  cudaGetSymbolAddress(&pA, g_Ah);
  cudaGetSymbolAddress(&pW, g_Wh);

  int nA8 = Mm*Dd/8, nW8 = N3*Dd/8;
  to_half_k<<<(nA8+255)/256, 256>>>((const float4*)inp, (uint4*)pA, nA8);
  to_half_k<<<(nW8+255)/256, 256>>>((const float4*)W,   (uint4*)pW, nW8);

  static int smem_set = 0;
  if (!smem_set){
    cudaFuncSetAttribute(gemm_qrnn, cudaFuncAttributeMaxDynamicSharedMemorySize, GEMM_SMEM);
    smem_set = 1;
  }
  gemm_qrnn<<<dim3(N3/BN, Mm/BM), 256, GEMM_SMEM>>>((const __half*)pA, (const __half*)pW, bias);

  scanA_k<<<Bb*SC, 512>>>();
  int wr = (out_size >= Mm*Hh + Bb*Hh) ? 1 : 0;
  scanB_k<<<Bb*Hh/1024, 1024>>>(out + (size_t)Mm*Hh, wr);
  scanC_k<<<Bb*SC, 512>>>(out);
}

// round 15
// speedup vs baseline: 1.4150x; 1.4150x over previous
#include <cuda_runtime.h>
#include <cuda_fp16.h>
#include <cstdint>
#include <cstddef>

#define Bb 16
#define Ss 2048
#define Dd 1024
#define Hh 1024
#define Mm (Bb*Ss)      // 32768
#define N3 (3*Hh)       // 3072
#define SC 32
#define CH (Ss/SC)      // 64

// ---- device scratch (static: allowed) ----
__device__ __half g_z[(size_t)Mm*Hh];
__device__ __half g_f[(size_t)Mm*Hh];
__device__ __half g_o[(size_t)Mm*Hh];
__device__ __half g_Ah[(size_t)Mm*Dd];
__device__ __half g_Wh[(size_t)N3*Dd];
__device__ float  g_Ac[Bb*SC*Hh];
__device__ float  g_Bc[Bb*SC*Hh];
__device__ float  g_hs[Bb*SC*Hh];

__device__ __forceinline__ uint32_t smem_u32(const void* p){
  uint32_t a;
  asm("{ .reg .u64 t; cvta.to.shared.u64 t, %1; cvt.u32.u64 %0, t; }" : "=r"(a) : "l"(p));
  return a;
}

__device__ __forceinline__ void mma_f16(float* c, const uint32_t* a, const uint32_t* b){
  asm volatile("mma.sync.aligned.m16n8k16.row.col.f32.f16.f16.f32 "
    "{%0,%1,%2,%3}, {%4,%5,%6,%7}, {%8,%9}, {%0,%1,%2,%3};"
    : "+f"(c[0]),"+f"(c[1]),"+f"(c[2]),"+f"(c[3])
    : "r"(a[0]),"r"(a[1]),"r"(a[2]),"r"(a[3]),"r"(b[0]),"r"(b[1]));
}

// ---- f32 -> f16 convert, both tensors in one launch ----
__global__ void to_half_k(const float4* __restrict__ srcA, uint4* __restrict__ dstA, int n8a,
                          const float4* __restrict__ srcW, uint4* __restrict__ dstW, int n8w){
  int i = blockIdx.x*blockDim.x + threadIdx.x;
  const float4* src; uint4* dst; int j;
  if (i < n8a){ src = srcA; dst = dstA; j = i; }
  else { j = i - n8a; if (j >= n8w) return; src = srcW; dst = dstW; }
  float4 v0 = src[2*j], v1 = src[2*j+1];
  __half2 h0 = __floats2half2_rn(v0.x, v0.y);
  __half2 h1 = __floats2half2_rn(v0.z, v0.w);
  __half2 h2 = __floats2half2_rn(v1.x, v1.y);
  __half2 h3 = __floats2half2_rn(v1.z, v1.w);
  uint4 u;
  u.x = *(uint32_t*)&h0; u.y = *(uint32_t*)&h1;
  u.z = *(uint32_t*)&h2; u.w = *(uint32_t*)&h3;
  dst[j] = u;
}

// ---- GEMM: 128x128x(BK=32) fp16 tiles, cp.async 4-stage, ldmatrix (R5 config) ----
constexpr int BM=128, BN=128, BK=32;
constexpr int KT = Dd/BK;               // 32 k-tiles
constexpr int ROWH = 40;                // halves per smem row (32 + 8 pad) = 80B
constexpr int STG_H = BM*ROWH;          // 5120 halves per operand per stage
constexpr int STAGE_H = 2*STG_H;        // 10240 halves = 20480B per stage
constexpr int NSTG = 4;
constexpr int GEMM_SMEM = NSTG*STAGE_H*2;  // 81920 bytes

__global__ __launch_bounds__(256,2) void gemm_qrnn(
    const __half* __restrict__ A,   // g_Ah [Mm, Dd]
    const __half* __restrict__ W,   // g_Wh [N3, Dd]
    const float* __restrict__ bias)
{
  extern __shared__ __half sm[];
  const int tid  = threadIdx.x;
  const int lane = tid & 31;
  const int warp = tid >> 5;
  const int wm = warp >> 2;       // 0..1
  const int wn = warp & 3;        // 0..3
  const int bm = blockIdx.y * BM;
  const int bn = blockIdx.x * BN;
  const uint32_t smb = smem_u32(sm);

  float acc[4][4][4];
  #pragma unroll
  for (int i=0;i<4;i++)
    #pragma unroll
    for (int j=0;j<4;j++)
      #pragma unroll
      for (int k=0;k<4;k++) acc[i][j][k]=0.f;

  auto issue = [&](int kt, int s){
    __half* as = sm + s*STAGE_H;
    __half* bs = as + STG_H;
    #pragma unroll
    for (int i=0;i<2;i++){
      int idx = tid + i*256;            // 0..511 : row 0..127, chunk 0..3
      int row = idx >> 2;
      int ch  = idx & 3;
      const __half* ga = A + (size_t)(bm+row)*Dd + kt*BK + ch*8;
      const __half* gb = W + (size_t)(bn+row)*Dd + kt*BK + ch*8;
      uint32_t sa = smem_u32(as + row*ROWH + ch*8);
      uint32_t sb = smem_u32(bs + row*ROWH + ch*8);
      asm volatile("cp.async.cg.shared.global [%0], [%1], 16;" :: "r"(sa), "l"(ga));
      asm volatile("cp.async.cg.shared.global [%0], [%1], 16;" :: "r"(sb), "l"(gb));
    }
  };

  auto compute = [&](int s){
    const uint32_t abase = smb + s*(STAGE_H*2);
    const uint32_t bbase = abase + STG_H*2;
    #pragma unroll
    for (int q=0; q<2; q++){            // 2 k16 chunks in BK=32
      uint32_t a[4][4], b[4][2];
      #pragma unroll
      for (int mi=0;mi<4;mi++){
        int rowA = wm*64 + mi*16 + (lane & 15);
        uint32_t addr = abase + rowA*80 + q*32 + (lane>>4)*16;
        asm volatile("ldmatrix.sync.aligned.m8n8.x4.shared.b16 {%0,%1,%2,%3}, [%4];"
          : "=r"(a[mi][0]),"=r"(a[mi][1]),"=r"(a[mi][2]),"=r"(a[mi][3]) : "r"(addr));
      }
      #pragma unroll
      for (int np=0; np<2; np++){
        int rowB = wn*32 + np*16 + (lane & 7) + ((lane>>4)&1)*8;
        uint32_t addr = bbase + rowB*80 + q*32 + ((lane>>3)&1)*16;
        asm volatile("ldmatrix.sync.aligned.m8n8.x4.shared.b16 {%0,%1,%2,%3}, [%4];"
          : "=r"(b[np*2][0]),"=r"(b[np*2][1]),"=r"(b[np*2+1][0]),"=r"(b[np*2+1][1]) : "r"(addr));
      }
      #pragma unroll
      for (int mi=0;mi<4;mi++)
        #pragma unroll
        for (int ni=0;ni<4;ni++)
          mma_f16(acc[mi][ni], a[mi], b[ni]);
    }
  };

  issue(0,0); asm volatile("cp.async.commit_group;" ::: "memory");
  issue(1,1); asm volatile("cp.async.commit_group;" ::: "memory");
  issue(2,2); asm volatile("cp.async.commit_group;" ::: "memory");

  for (int kt=0; kt<KT; kt++){
    asm volatile("cp.async.wait_group 2;" ::: "memory");
    __syncthreads();
    if (kt+3 < KT) issue(kt+3, (kt+3)%NSTG);
    asm volatile("cp.async.commit_group;" ::: "memory");
    compute(kt%NSTG);
  }

  // Epilogue: bias + activation -> fp16 gate scratch (half2 stores).
  const int gate = bn >> 10;            // 128-col tile lies within one gate
  __half* dst = (gate==0) ? g_z : ((gate==1) ? g_f : g_o);
  const int r0 = bm + wm*64 + (lane>>2);
  const int c0 = bn + wn*32 + (lane&3)*2;

  // hoist bias: 8 values per thread (ni 0..3 x 2 cols)
  float bv[8];
  #pragma unroll
  for (int ni=0;ni<4;ni++){
    bv[ni*2+0] = __ldg(&bias[c0 + ni*8 + 0]);
    bv[ni*2+1] = __ldg(&bias[c0 + ni*8 + 1]);
  }

  #pragma unroll
  for (int mi=0;mi<4;mi++){
    #pragma unroll
    for (int ni=0;ni<4;ni++){
      #pragma unroll
      for (int half=0; half<2; half++){
        const int row = r0 + mi*16 + half*8;
        const int col = c0 + ni*8;
        float y0 = acc[mi][ni][half*2+0] + bv[ni*2+0];
        float y1 = acc[mi][ni][half*2+1] + bv[ni*2+1];
        float v0, v1;
        if (gate==0){ v0 = tanhf(y0); v1 = tanhf(y1); }
        else        { v0 = __fdividef(1.f, 1.f+__expf(-y0));
                      v1 = __fdividef(1.f, 1.f+__expf(-y1)); }
        const int hcol = col & (Hh-1);
        *(__half2*)&dst[(size_t)row*Hh + hcol] = __floats2half2_rn(v0, v1);
      }
    }
  }
}

// ---- two-pass chunked scan (half2 vectorized, f32 math) ----
__global__ __launch_bounds__(512) void scanA_k(){
  int b = blockIdx.x / SC, c = blockIdx.x % SC, h2 = threadIdx.x;
  size_t base2 = ((size_t)(b*Ss + c*CH))*(Hh/2) + h2;
  const __half2* Z = (const __half2*)g_z;
  const __half2* F = (const __half2*)g_f;
  float2 A = make_float2(1.f,1.f), hh = make_float2(0.f,0.f);
  #pragma unroll 4
  for (int s=0; s<CH; s++){
    float2 f = __half22float2(F[base2 + (size_t)s*(Hh/2)]);
    float2 z = __half22float2(Z[base2 + (size_t)s*(Hh/2)]);
    hh.x = fmaf(f.x, z.x - hh.x, hh.x);
    hh.y = fmaf(f.y, z.y - hh.y, hh.y);
    A.x *= (1.f - f.x);
    A.y *= (1.f - f.y);
  }
  int o = blockIdx.x*(Hh/2) + h2;
  ((float2*)g_Ac)[o] = A; ((float2*)g_Bc)[o] = hh;
}

__global__ __launch_bounds__(1024) void scanB_k(float* __restrict__ clast, int wr){
  int t = blockIdx.x*blockDim.x + threadIdx.x;   // 16384
  int b = t >> 10, h = t & (Hh-1);
  float hh = 0.f;
  #pragma unroll
  for (int c=0; c<SC; c++){
    int idx = (b*SC + c)*Hh + h;
    g_hs[idx] = hh;
    hh = fmaf(g_Ac[idx], hh, g_Bc[idx]);
  }
  if (wr) clast[t] = hh;
}

__global__ __launch_bounds__(512) void scanC_k(float* __restrict__ out){
  int b = blockIdx.x / SC, c = blockIdx.x % SC, h2 = threadIdx.x;
  size_t base2 = ((size_t)(b*Ss + c*CH))*(Hh/2) + h2;
  const __half2* Z = (const __half2*)g_z;
  const __half2* F = (const __half2*)g_f;
  const __half2* O = (const __half2*)g_o;
  float2 hh = ((const float2*)g_hs)[blockIdx.x*(Hh/2) + h2];
  float2* out2 = (float2*)out;
  #pragma unroll 4
  for (int s=0; s<CH; s++){
    size_t idx = base2 + (size_t)s*(Hh/2);
    float2 f = __half22float2(F[idx]);
    float2 z = __half22float2(Z[idx]);
    float2 o = __half22float2(O[idx]);
    hh.x = fmaf(f.x, z.x - hh.x, hh.x);
    hh.y = fmaf(f.y, z.y - hh.y, hh.y);
    out2[idx] = make_float2(o.x*hh.x, o.y*hh.y);
  }
}

// ---- host ----
extern "C" void kernel_launch(void* const* d_in, const int* in_sizes, int n_in,
                              void* d_out, int out_size) {
  const float* inp  = (const float*)d_in[0];
  const float* W    = (const float*)d_in[1];
  const float* bias = (const float*)d_in[2];
  float* out = (float*)d_out;

  void *pA=nullptr, *pW=nullptr;
  cudaGetSymbolAddress(&pA, g_Ah);
  cudaGetSymbolAddress(&pW, g_Wh);

  int nA8 = Mm*Dd/8, nW8 = N3*Dd/8;
  to_half_k<<<(nA8+nW8+255)/256, 256>>>((const float4*)inp, (uint4*)pA, nA8,
                                        (const float4*)W,   (uint4*)pW, nW8);

  static int smem_set = 0;
  if (!smem_set){
    cudaFuncSetAttribute(gemm_qrnn, cudaFuncAttributeMaxDynamicSharedMemorySize, GEMM_SMEM);
    smem_set = 1;
  }
  gemm_qrnn<<<dim3(N3/BN, Mm/BM), 256, GEMM_SMEM>>>((const __half*)pA, (const __half*)pW, bias);

  scanA_k<<<Bb*SC, 512>>>();
  int wr = (out_size >= Mm*Hh + Bb*Hh) ? 1 : 0;
  scanB_k<<<Bb*Hh/1024, 1024>>>(out + (size_t)Mm*Hh, wr);
  scanC_k<<<Bb*SC, 512>>>(out);
}